// round 3
// baseline (speedup 1.0000x reference)
#include <cuda_runtime.h>
#include <cuda_bf16.h>

#define DD 4096
#define MAXR 16384

// ---------------- device scratch (no allocations allowed) ----------------
__device__ float4 g_cG[DD];     // ga, gb, goa, gob  (folded gate affine coeffs)
__device__ float  g_maskf[DD];  // top-k hard mask as float
__device__ float  g_emaN[DD];   // normalized ema_out_dir
__device__ float  g_novel[DD];  // sum over rows of |x - mean|
__device__ float  g_invIn[DD];  // 1/(sqrt(var_in)+eps)
__device__ float2 g_row[MAXR];  // per-row (dot, norm2)
__device__ float  g_sc[8];      // tau, beta_up, beta_dn, beta_out

// ---------------- helpers ----------------
__device__ __forceinline__ float tanh_apx(float x) {
    float r;
    asm("tanh.approx.f32 %0, %1;" : "=f"(r) : "f"(x));
    return r;
}

// accurate tanh: ~1e-7 abs err (2 MUFU: EX2 + RCP)
__device__ __forceinline__ float tanh_acc(float u) {
    float e = __expf(2.0f * u);               // inf for large u -> tanh=1
    return 1.0f - __fdividef(2.0f, e + 1.0f); // -1 for very negative u
}

__device__ __forceinline__ float gelu_f(float x) {
    // 0.5*x*(1+tanh(c*(x + 0.044715 x^3))),  c = sqrt(2/pi)
    float u = 0.7978845608028654f * x * fmaf(0.044715f, x * x, 1.0f);
    return 0.5f * x * (1.0f + tanh_acc(u));
}

__device__ __forceinline__ float softplus_f(float x) { return log1pf(expf(x)); }

// streaming (evict-first) float4 store: keeps x resident in L2 for reuse
__device__ __forceinline__ void st_cs_f4(float4* p, float4 v) {
    asm volatile("st.global.cs.v4.f32 [%0], {%1,%2,%3,%4};"
                 :: "l"(p), "f"(v.x), "f"(v.y), "f"(v.z), "f"(v.w)
                 : "memory");
}

// ---------------- K0: scalars + per-channel constants + zeroing ----------------
__global__ void k0_prep(const float* lt, const float* lbu, const float* lbd,
                        const float* lg, const float* lbo, const float* lgo,
                        const float* __restrict__ ema_mean,
                        const float* __restrict__ ema_sq,
                        const float* __restrict__ ema_om,
                        const float* __restrict__ ema_osq,
                        const float* __restrict__ ema_dir,
                        int R)
{
    __shared__ float s_red[8];
    __shared__ float s_par[4];
    int t = threadIdx.x;

    // ||ema_out_dir||^2
    float acc = 0.f;
#pragma unroll
    for (int s = 0; s < 16; s++) {
        float v = ema_dir[t + s * 256];
        acc = fmaf(v, v, acc);
    }
#pragma unroll
    for (int o = 16; o; o >>= 1) acc += __shfl_down_sync(0xffffffffu, acc, o);
    if ((t & 31) == 0) s_red[t >> 5] = acc;
    __syncthreads();

    if (t == 0) {
        float n2 = 0.f;
        for (int i = 0; i < 8; i++) n2 += s_red[i];
        float rn = 1.0f / fmaxf(sqrtf(n2), 1e-12f);
        g_sc[0] = expf(lt[0]);          // tau
        g_sc[1] = softplus_f(lbu[0]);   // beta_up
        g_sc[2] = softplus_f(lbd[0]);   // beta_dn
        g_sc[3] = softplus_f(lbo[0]);   // beta_out
        s_par[0] = softplus_f(lg[0]);   // gamma
        s_par[1] = softplus_f(lgo[0]);  // gamma_out
        s_par[2] = rn;
    }
    __syncthreads();

    float gamma = s_par[0], gammo = s_par[1], rn = s_par[2];
#pragma unroll
    for (int s = 0; s < 16; s++) {
        int c = t + s * 256;
        float m = ema_mean[c];
        float var = fmaxf(ema_sq[c] - m * m, 1e-4f);
        float inv = 1.0f / (sqrtf(var) + 1e-5f);
        float mo = ema_om[c];
        float varo = fmaxf(ema_osq[c] - mo * mo, 1e-4f);
        float invo = 1.0f / (sqrtf(varo) + 1e-5f);
        float4 cg;
        cg.x = gamma * inv;           // ga : gamma*z_in = x*ga + gb
        cg.y = -gamma * m * inv;      // gb
        cg.z = gammo * invo;          // goa: gamma_out*z_out = o*goa + gob
        cg.w = -gammo * mo * invo;    // gob
        g_cG[c] = cg;
        g_emaN[c] = ema_dir[c] * rn;
        g_invIn[c] = inv;
        g_novel[c] = 0.f;
    }
    for (int i = t; i < R; i += 256) g_row[i] = make_float2(0.f, 0.f);
}

// ---------------- K1: row dot/norm + channel |x-mean| sums ----------------
// grid = R/16 blocks, 256 threads; 16 rows/block; each thread owns 16 fixed cols.
#define K1_ROWS 16
__global__ void __launch_bounds__(256)
k1_reduce(const float* __restrict__ x,
          const float* __restrict__ ema_mean)
{
    int t = threadIdx.x;
    int row0 = blockIdx.x * K1_ROWS;

    // thread t owns channels {s*1024 + 4t .. 4t+3}, s = 0..3
    float mv[16], en[16];
    const float4* m4 = (const float4*)ema_mean;
    const float4* e4 = (const float4*)g_emaN;
#pragma unroll
    for (int s = 0; s < 4; s++) {
        float4 a = m4[s * 256 + t];
        float4 b = e4[s * 256 + t];
        mv[s*4+0]=a.x; mv[s*4+1]=a.y; mv[s*4+2]=a.z; mv[s*4+3]=a.w;
        en[s*4+0]=b.x; en[s*4+1]=b.y; en[s*4+2]=b.z; en[s*4+3]=b.w;
    }

    float accA[16];
#pragma unroll
    for (int j = 0; j < 16; j++) accA[j] = 0.f;

    for (int r = 0; r < K1_ROWS; r++) {
        const float4* xr = (const float4*)x + (size_t)(row0 + r) * (DD / 4);
        float dot = 0.f, nrm = 0.f;
#pragma unroll
        for (int s = 0; s < 4; s++) {
            float4 xv = xr[s * 256 + t];
            float xs[4] = {xv.x, xv.y, xv.z, xv.w};
#pragma unroll
            for (int i = 0; i < 4; i++) {
                int j = s * 4 + i;
                float o = gelu_f(xs[i]);
                dot = fmaf(o, en[j], dot);
                nrm = fmaf(o, o, nrm);
                accA[j] += fabsf(xs[i] - mv[j]);
            }
        }
#pragma unroll
        for (int o = 16; o; o >>= 1) {
            dot += __shfl_down_sync(0xffffffffu, dot, o);
            nrm += __shfl_down_sync(0xffffffffu, nrm, o);
        }
        if ((t & 31) == 0) {
            atomicAdd(&g_row[row0 + r].x, dot);
            atomicAdd(&g_row[row0 + r].y, nrm);
        }
    }

#pragma unroll
    for (int s = 0; s < 4; s++)
#pragma unroll
        for (int i = 0; i < 4; i++)
            atomicAdd(&g_novel[s * 1024 + 4 * t + i], accA[s * 4 + i]);
}

// ---------------- K2: exact top-k via bitonic sort of (score,index) ----------------
__global__ void k2_topk(const int* __restrict__ kptr, int R)
{
    __shared__ unsigned long long key[DD];
    int t = threadIdx.x;
    float invR = 1.0f / (float)R;

    for (int i = t; i < DD; i += 1024) {
        float s = g_novel[i] * g_invIn[i] * invR;   // novel_score[i] (>= 0)
        // descending by score; ties -> smaller index first (matches top_k)
        key[i] = ((unsigned long long)__float_as_uint(s) << 32)
               | (unsigned)(0xFFFFFFFFu - (unsigned)i);
    }
    __syncthreads();

    for (int ks = 2; ks <= DD; ks <<= 1) {
        for (int j = ks >> 1; j > 0; j >>= 1) {
            for (int i = t; i < DD; i += 1024) {
                int ixj = i ^ j;
                if (ixj > i) {
                    unsigned long long a = key[i], b = key[ixj];
                    bool sw = ((i & ks) == 0) ? (a < b) : (a > b);
                    if (sw) { key[i] = b; key[ixj] = a; }
                }
            }
            __syncthreads();
        }
    }

    for (int i = t; i < DD; i += 1024) g_maskf[i] = 0.f;
    __syncthreads();
    int kk = *kptr;
    for (int i = t; i < kk; i += 1024) {
        unsigned idx = 0xFFFFFFFFu - (unsigned)(key[i] & 0xFFFFFFFFull);
        g_maskf[idx] = 1.0f;
    }
}

// ---------------- K3: apply gates, write output ----------------
// grid = R/16 blocks, 256 threads. REVERSED block->row map so K3 re-reads x
// tail-first (most recently L2-cached by K1); streaming stores for out keep
// x resident in L2.
__global__ void __launch_bounds__(256)
k3_final(const float* __restrict__ x, float* __restrict__ out)
{
    int t = threadIdx.x;
    int row0 = (gridDim.x - 1 - blockIdx.x) * 16;   // reverse traversal
    float tau = g_sc[0], bup = g_sc[1], bdn = g_sc[2], bout = g_sc[3];

    float ga[16], gb[16], goa[16], gob[16], mk[16];
    const float4* cg4 = (const float4*)g_cG;
    const float4* mk4 = (const float4*)g_maskf;
#pragma unroll
    for (int s = 0; s < 4; s++) {
        float4 m = mk4[s * 256 + t];
        mk[s*4+0]=m.x; mk[s*4+1]=m.y; mk[s*4+2]=m.z; mk[s*4+3]=m.w;
#pragma unroll
        for (int i = 0; i < 4; i++) {
            float4 c = cg4[s * 1024 + 4 * t + i];
            int j = s * 4 + i;
            ga[j]=c.x; gb[j]=c.y; goa[j]=c.z; gob[j]=c.w;
        }
    }

    for (int r = 15; r >= 0; r--) {           // reverse inside block too
        int row = row0 + r;
        float2 rs = g_row[row];
        float cs = rs.x / fmaxf(sqrtf(rs.y), 1e-12f);
        cs = fminf(fmaxf(cs, -1.0f), 1.0f);
        float gcos = __expf(-tau * cs);

        const float4* xr = (const float4*)x + (size_t)row * (DD / 4);
        float4* orr = (float4*)out + (size_t)row * (DD / 4);
#pragma unroll
        for (int s = 0; s < 4; s++) {
            float4 xv = xr[s * 256 + t];
            float xs[4] = {xv.x, xv.y, xv.z, xv.w};
            float os[4];
#pragma unroll
            for (int i = 0; i < 4; i++) {
                int j = s * 4 + i;
                float xx = xs[i];
                float o = gelu_f(xx);
                // gate_in
                float t1 = tanh_apx(fmaf(xx, ga[j], gb[j]));
                float gin = fmaf((t1 > 0.f) ? bup : bdn, t1, 1.0f);
                gin = fminf(fmaxf(gin, 0.05f), 8.0f);
                // gate_out
                float t2 = tanh_apx(fmaf(o, goa[j], gob[j]));
                float gou = fminf(fmaxf(fmaf(bout, t2, 1.0f), 0.1f), 5.0f);
                // gate_eff = mask ? gin*gou*gcos : 1
                float g = fmaf(mk[j], gin * gou * gcos - 1.0f, 1.0f);
                os[i] = o * g;
            }
            st_cs_f4(&orr[s * 256 + t], make_float4(os[0], os[1], os[2], os[3]));
        }
    }
}

// ---------------- launch ----------------
extern "C" void kernel_launch(void* const* d_in, const int* in_sizes, int n_in,
                              void* d_out, int out_size)
{
    const float* x        = (const float*)d_in[0];
    // d_in[1] = logit_decay (unused in reference forward)
    const float* log_tau  = (const float*)d_in[2];
    const float* lbu      = (const float*)d_in[3];
    const float* lbd      = (const float*)d_in[4];
    const float* lg       = (const float*)d_in[5];
    const float* lbo      = (const float*)d_in[6];
    const float* lgo      = (const float*)d_in[7];
    // d_in[8] = log_temperature (cancels numerically in mask_st)
    const float* ema_mean = (const float*)d_in[9];
    const float* ema_sq   = (const float*)d_in[10];
    const float* ema_om   = (const float*)d_in[11];
    const float* ema_osq  = (const float*)d_in[12];
    const float* ema_dir  = (const float*)d_in[13];
    const int*   kptr     = (const int*)d_in[14];
    float* out = (float*)d_out;

    int R = in_sizes[0] / DD;   // 8192 rows

    k0_prep<<<1, 256>>>(log_tau, lbu, lbd, lg, lbo, lgo,
                        ema_mean, ema_sq, ema_om, ema_osq, ema_dir, R);
    k1_reduce<<<R / K1_ROWS, 256>>>(x, ema_mean);
    k2_topk<<<1, 1024>>>(kptr, R);
    k3_final<<<R / 16, 256>>>(x, out);
}

// round 9
// speedup vs baseline: 1.2999x; 1.2999x over previous
#include <cuda_runtime.h>
#include <cuda_bf16.h>

#define DD 4096
#define MAXR 16384
#define ROWS_PB 64   // rows per block in K1/K3

// ---------------- device scratch (no allocations allowed) ----------------
__device__ float4 g_cG[DD];        // ga, gb, goa, gob (folded gate affine coeffs)
__device__ float  g_maskf[DD];     // top-k hard mask as float
__device__ float  g_emaN[DD];      // normalized ema_out_dir
__device__ float  g_novel[DD];     // sum over rows of |x - mean|
__device__ float  g_invIn[DD];     // 1/(sqrt(var_in)+eps)
__device__ float2 g_rowp[4][MAXR]; // per-slice per-row (dot, norm2) partials
__device__ float  g_sc[8];         // tau, beta_up, beta_dn, beta_out

// ---------------- helpers ----------------
__device__ __forceinline__ float tanh_apx(float x) {
    float r;
    asm("tanh.approx.f32 %0, %1;" : "=f"(r) : "f"(x));
    return r;
}

__device__ __forceinline__ float gelu_f(float x) {
    // 0.5*x*(1+tanh(c*(x + 0.044715 x^3))),  c = sqrt(2/pi)
    float u = 0.7978845608028654f * x * fmaf(0.044715f, x * x, 1.0f);
    return 0.5f * x * (1.0f + tanh_apx(u));
}

__device__ __forceinline__ float softplus_f(float x) { return log1pf(expf(x)); }

// streaming (evict-first) float4 store: keeps x resident in L2 for reuse
__device__ __forceinline__ void st_cs_f4(float4* p, float4 v) {
    asm volatile("st.global.cs.v4.f32 [%0], {%1,%2,%3,%4};"
                 :: "l"(p), "f"(v.x), "f"(v.y), "f"(v.z), "f"(v.w)
                 : "memory");
}

// ---------------- K0: scalars + per-channel constants + zeroing ----------------
__global__ void k0_prep(const float* lt, const float* lbu, const float* lbd,
                        const float* lg, const float* lbo, const float* lgo,
                        const float* __restrict__ ema_mean,
                        const float* __restrict__ ema_sq,
                        const float* __restrict__ ema_om,
                        const float* __restrict__ ema_osq,
                        const float* __restrict__ ema_dir,
                        int R)
{
    __shared__ float s_red[8];
    __shared__ float s_par[4];
    int t = threadIdx.x;

    // ||ema_out_dir||^2
    float acc = 0.f;
#pragma unroll
    for (int s = 0; s < 16; s++) {
        float v = ema_dir[t + s * 256];
        acc = fmaf(v, v, acc);
    }
#pragma unroll
    for (int o = 16; o; o >>= 1) acc += __shfl_down_sync(0xffffffffu, acc, o);
    if ((t & 31) == 0) s_red[t >> 5] = acc;
    __syncthreads();

    if (t == 0) {
        float n2 = 0.f;
        for (int i = 0; i < 8; i++) n2 += s_red[i];
        float rn = 1.0f / fmaxf(sqrtf(n2), 1e-12f);
        g_sc[0] = expf(lt[0]);          // tau
        g_sc[1] = softplus_f(lbu[0]);   // beta_up
        g_sc[2] = softplus_f(lbd[0]);   // beta_dn
        g_sc[3] = softplus_f(lbo[0]);   // beta_out
        s_par[0] = softplus_f(lg[0]);   // gamma
        s_par[1] = softplus_f(lgo[0]);  // gamma_out
        s_par[2] = rn;
    }
    __syncthreads();

    float gamma = s_par[0], gammo = s_par[1], rn = s_par[2];
#pragma unroll
    for (int s = 0; s < 16; s++) {
        int c = t + s * 256;
        float m = ema_mean[c];
        float var = fmaxf(ema_sq[c] - m * m, 1e-4f);
        float inv = 1.0f / (sqrtf(var) + 1e-5f);
        float mo = ema_om[c];
        float varo = fmaxf(ema_osq[c] - mo * mo, 1e-4f);
        float invo = 1.0f / (sqrtf(varo) + 1e-5f);
        float4 cg;
        cg.x = gamma * inv;           // ga : gamma*z_in = x*ga + gb
        cg.y = -gamma * m * inv;      // gb
        cg.z = gammo * invo;          // goa: gamma_out*z_out = o*goa + gob
        cg.w = -gammo * mo * invo;    // gob
        g_cG[c] = cg;
        g_emaN[c] = ema_dir[c] * rn;
        g_invIn[c] = inv;
        g_novel[c] = 0.f;
    }
}

// ---------------- K1: row dot/norm partials + channel |x-mean| sums ----------------
// grid = (R/64, 4), 256 threads. Block covers 64 rows x 1024 channels.
// Thread t owns 4 channels: c = slice*1024 + 4t .. +3.
// Row partials go to g_rowp[slice][row] with plain stores (no atomics).
__global__ void __launch_bounds__(256)
k1_reduce(const float* __restrict__ x,
          const float* __restrict__ ema_mean)
{
    int t = threadIdx.x;
    int wid = t >> 5, lid = t & 31;
    int slice = blockIdx.y;
    int row0 = blockIdx.x * ROWS_PB;
    int c4 = slice * 256 + t;            // float4 index within a row

    float4 a = ((const float4*)ema_mean)[c4];
    float4 b = ((const float4*)g_emaN)[c4];
    float mv[4] = {a.x, a.y, a.z, a.w};
    float en[4] = {b.x, b.y, b.z, b.w};
    float accA[4] = {0.f, 0.f, 0.f, 0.f};

    __shared__ float s_dot[ROWS_PB][8];
    __shared__ float s_nrm[ROWS_PB][8];

    const float4* x4 = (const float4*)x;
    for (int r = 0; r < ROWS_PB; r++) {
        float4 xv = x4[(size_t)(row0 + r) * (DD / 4) + c4];
        float xs[4] = {xv.x, xv.y, xv.z, xv.w};
        float dot = 0.f, nrm = 0.f;
#pragma unroll
        for (int i = 0; i < 4; i++) {
            float o = gelu_f(xs[i]);
            dot = fmaf(o, en[i], dot);
            nrm = fmaf(o, o, nrm);
            accA[i] += fabsf(xs[i] - mv[i]);
        }
#pragma unroll
        for (int o = 16; o; o >>= 1) {
            dot += __shfl_down_sync(0xffffffffu, dot, o);
            nrm += __shfl_down_sync(0xffffffffu, nrm, o);
        }
        if (lid == 0) { s_dot[r][wid] = dot; s_nrm[r][wid] = nrm; }
    }
    __syncthreads();

    // threads 0..63 finalize this slice's partial for each row (plain store)
    if (t < ROWS_PB) {
        float vd = 0.f, vn = 0.f;
#pragma unroll
        for (int w = 0; w < 8; w++) { vd += s_dot[t][w]; vn += s_nrm[t][w]; }
        g_rowp[slice][row0 + t] = make_float2(vd, vn);
    }

#pragma unroll
    for (int i = 0; i < 4; i++)
        atomicAdd(&g_novel[4 * c4 + i], accA[i]);
}

// ---------------- K2: exact top-k, hybrid bitonic (shuffle for j<=16) --------
// Descending sort of packed (score, ~index) keys. keep-max rule for shuffle
// phases: keep max iff ((i&j)==0) == ((i&ks)==0)  (matches the smem version's
// "descending block when (i&ks)==0" convention). For j<=16 the partner is
// same-chunk same-warp since i = c*1024 + t.
__global__ void k2_topk(const int* __restrict__ kptr, int R)
{
    __shared__ unsigned long long key[DD];
    int t = threadIdx.x;
    float invR = 1.0f / (float)R;

    unsigned long long v[4];
#pragma unroll
    for (int c = 0; c < 4; c++) {
        int i = c * 1024 + t;
        g_maskf[i] = 0.f;
        float s = g_novel[i] * g_invIn[i] * invR;   // novel_score[i] (>= 0)
        v[c] = ((unsigned long long)__float_as_uint(s) << 32)
             | (unsigned)(0xFFFFFFFFu - (unsigned)i);
    }

    // ks = 2..32: fully intra-warp, registers only, no barriers
#pragma unroll
    for (int ks = 2; ks <= 32; ks <<= 1) {
#pragma unroll
        for (int j = ks >> 1; j; j >>= 1) {
#pragma unroll
            for (int c = 0; c < 4; c++) {
                int i = c * 1024 + t;
                unsigned long long p = __shfl_xor_sync(0xffffffffu, v[c], j);
                bool keepmax = (((i & j) == 0) == ((i & ks) == 0));
                v[c] = keepmax ? (v[c] > p ? v[c] : p)
                               : (v[c] < p ? v[c] : p);
            }
        }
    }
#pragma unroll
    for (int c = 0; c < 4; c++) key[c * 1024 + t] = v[c];
    __syncthreads();

    // ks = 64..4096: smem phases for j>=32, shuffle cascade for j<=16
    for (int ks = 64; ks <= DD; ks <<= 1) {
        int j = ks >> 1;
        for (; j >= 32; j >>= 1) {
#pragma unroll
            for (int c = 0; c < 4; c++) {
                int i = c * 1024 + t;
                int ixj = i ^ j;
                if (ixj > i) {
                    unsigned long long a = key[i], b = key[ixj];
                    bool sw = ((i & ks) == 0) ? (a < b) : (a > b);
                    if (sw) { key[i] = b; key[ixj] = a; }
                }
            }
            __syncthreads();
        }
#pragma unroll
        for (int c = 0; c < 4; c++) v[c] = key[c * 1024 + t];
#pragma unroll
        for (int jj = 16; jj; jj >>= 1) {
#pragma unroll
            for (int c = 0; c < 4; c++) {
                int i = c * 1024 + t;
                unsigned long long p = __shfl_xor_sync(0xffffffffu, v[c], jj);
                bool keepmax = (((i & jj) == 0) == ((i & ks) == 0));
                v[c] = keepmax ? (v[c] > p ? v[c] : p)
                               : (v[c] < p ? v[c] : p);
            }
        }
#pragma unroll
        for (int c = 0; c < 4; c++) key[c * 1024 + t] = v[c];
        __syncthreads();
    }

    int kk = *kptr;
    for (int i = t; i < kk; i += 1024) {
        unsigned idx = 0xFFFFFFFFu - (unsigned)(key[i] & 0xFFFFFFFFull);
        g_maskf[idx] = 1.0f;
    }
}

// ---------------- K3: apply gates, write output ----------------
// grid = (R/64, 4), 256 threads. Same blocking as K1; 4 channels/thread keeps
// regs low -> high occupancy. Reverse row-chunk order to chase K1's L2
// frontier; streaming stores for out keep x resident in L2.
__global__ void __launch_bounds__(256)
k3_final(const float* __restrict__ x, float* __restrict__ out)
{
    int t = threadIdx.x;
    int slice = blockIdx.y;
    int row0 = (gridDim.x - 1 - blockIdx.x) * ROWS_PB;   // reverse traversal
    int c4 = slice * 256 + t;

    float tau = g_sc[0], bup = g_sc[1], bdn = g_sc[2], bout = g_sc[3];

    float ga[4], gb[4], goa[4], gob[4], mk[4];
    {
        float4 m = ((const float4*)g_maskf)[c4];
        mk[0]=m.x; mk[1]=m.y; mk[2]=m.z; mk[3]=m.w;
#pragma unroll
        for (int i = 0; i < 4; i++) {
            float4 c = g_cG[4 * c4 + i];
            ga[i]=c.x; gb[i]=c.y; goa[i]=c.z; gob[i]=c.w;
        }
    }

    __shared__ float s_g[ROWS_PB];
    if (t < ROWS_PB) {
        int row = row0 + t;
        float2 p0 = g_rowp[0][row];
        float2 p1 = g_rowp[1][row];
        float2 p2 = g_rowp[2][row];
        float2 p3 = g_rowp[3][row];
        float dot = (p0.x + p1.x) + (p2.x + p3.x);
        float nrm = (p0.y + p1.y) + (p2.y + p3.y);
        float cs = dot / fmaxf(sqrtf(nrm), 1e-12f);
        cs = fminf(fmaxf(cs, -1.0f), 1.0f);
        s_g[t] = __expf(-tau * cs);
    }
    __syncthreads();

    const float4* x4 = (const float4*)x;
    float4* o4 = (float4*)out;
    for (int r = ROWS_PB - 1; r >= 0; r--) {
        int row = row0 + r;
        float gcos = s_g[r];
        float4 xv = x4[(size_t)row * (DD / 4) + c4];
        float xs[4] = {xv.x, xv.y, xv.z, xv.w};
        float os[4];
#pragma unroll
        for (int i = 0; i < 4; i++) {
            float xx = xs[i];
            float o = gelu_f(xx);
            // gate_in
            float t1 = tanh_apx(fmaf(xx, ga[i], gb[i]));
            float gin = fmaf((t1 > 0.f) ? bup : bdn, t1, 1.0f);
            gin = fminf(fmaxf(gin, 0.05f), 8.0f);
            // gate_out
            float t2 = tanh_apx(fmaf(o, goa[i], gob[i]));
            float gou = fminf(fmaxf(fmaf(bout, t2, 1.0f), 0.1f), 5.0f);
            // gate_eff = mask ? gin*gou*gcos : 1
            float g = fmaf(mk[i], gin * gou * gcos - 1.0f, 1.0f);
            os[i] = o * g;
        }
        st_cs_f4(&o4[(size_t)row * (DD / 4) + c4],
                 make_float4(os[0], os[1], os[2], os[3]));
    }
}

// ---------------- launch ----------------
extern "C" void kernel_launch(void* const* d_in, const int* in_sizes, int n_in,
                              void* d_out, int out_size)
{
    const float* x        = (const float*)d_in[0];
    // d_in[1] = logit_decay (unused in reference forward)
    const float* log_tau  = (const float*)d_in[2];
    const float* lbu      = (const float*)d_in[3];
    const float* lbd      = (const float*)d_in[4];
    const float* lg       = (const float*)d_in[5];
    const float* lbo      = (const float*)d_in[6];
    const float* lgo      = (const float*)d_in[7];
    // d_in[8] = log_temperature (cancels numerically in mask_st)
    const float* ema_mean = (const float*)d_in[9];
    const float* ema_sq   = (const float*)d_in[10];
    const float* ema_om   = (const float*)d_in[11];
    const float* ema_osq  = (const float*)d_in[12];
    const float* ema_dir  = (const float*)d_in[13];
    const int*   kptr     = (const int*)d_in[14];
    float* out = (float*)d_out;

    int R = in_sizes[0] / DD;   // 8192 rows

    dim3 grid(R / ROWS_PB, 4);

    k0_prep<<<1, 256>>>(log_tau, lbu, lbd, lg, lbo, lgo,
                        ema_mean, ema_sq, ema_om, ema_osq, ema_dir, R);
    k1_reduce<<<grid, 256>>>(x, ema_mean);
    k2_topk<<<1, 1024>>>(kptr, R);
    k3_final<<<grid, 256>>>(x, out);
}